// round 2
// baseline (speedup 1.0000x reference)
#include <cuda_runtime.h>
#include <math.h>

// ---------------- problem constants ----------------
#define QLEN   1024
#define BATCH  4
#define DMODEL 1024
#define NH     16
#define HD     64
#define MEMLEN 512
#define KLEN   1536            // MEMLEN + QLEN
#define MLPD   4096
#define ROWS   (QLEN*BATCH)    // 4096
#define CATROWS (KLEN*BATCH)   // 6144

// ---------------- scratch (device globals; no allocation allowed) ----------------
__device__ __align__(128) float g_cat [CATROWS*DMODEL];        // 24 MB
__device__ __align__(128) float g_qkv [CATROWS*3*DMODEL];      // 72 MB
__device__ __align__(128) float g_rh  [KLEN*DMODEL];           // 6 MB
__device__ __align__(128) float g_score[(size_t)BATCH*NH*QLEN*KLEN]; // 384 MB (AC, then probs in-place)
__device__ __align__(128) float g_bd  [(size_t)BATCH*NH*QLEN*KLEN];  // 384 MB (preBD, m-indexed)
__device__ __align__(128) float g_ctx [ROWS*DMODEL];
__device__ __align__(128) float g_y   [ROWS*DMODEL];
__device__ __align__(128) float g_x   [ROWS*DMODEL];
__device__ __align__(128) float g_h   [ROWS*MLPD];             // 64 MB
__device__ __align__(128) float g_y2  [ROWS*DMODEL];

// ---------------- concat [mem; inputs] -> g_cat ----------------
__global__ void cat_kernel(const float* __restrict__ mem, const float* __restrict__ inp)
{
    int idx4 = blockIdx.x * blockDim.x + threadIdx.x;
    if (idx4 >= CATROWS*DMODEL/4) return;
    long e = (long)idx4 * 4;
    int kv  = (int)(e / (BATCH*DMODEL));
    int rem = (int)(e % (BATCH*DMODEL));
    const float* src = (kv < MEMLEN)
        ? mem + (long)kv*BATCH*DMODEL + rem
        : inp + (long)(kv-MEMLEN)*BATCH*DMODEL + rem;
    *(float4*)(g_cat + e) = *(const float4*)src;
}

// ---------------- generic fp32 SGEMM: C[M,N] = A[M,K] @ B[K,N] (+bias)(+relu) ---
// EPI: 0 = none, 1 = +bias, 2 = +bias then relu
// M,N multiples of 128; K multiple of 8.
template<int EPI>
__global__ void sgemm128(const float* __restrict__ A, const float* __restrict__ B,
                         float* __restrict__ C, int M, int N, int K,
                         const float* __restrict__ bias)
{
    __shared__ float As[8][129];
    __shared__ float Bs[8][128];
    const int tid = threadIdx.x;
    const int m0 = blockIdx.y * 128, n0 = blockIdx.x * 128;
    const int row0 = (tid >> 4) * 8, col0 = (tid & 15) * 8;

    float acc[8][8];
    #pragma unroll
    for (int i = 0; i < 8; i++)
        #pragma unroll
        for (int j = 0; j < 8; j++) acc[i][j] = 0.f;

    const int arow = tid >> 1, ac4 = (tid & 1) * 4;
    const int brow = tid >> 5, bc  = (tid & 31) * 4;
    const float* Ap = A + (long)(m0 + arow) * K + ac4;
    const float* Bp = B + (long)brow * N + n0 + bc;

    for (int k0 = 0; k0 < K; k0 += 8) {
        float4 av = *(const float4*)(Ap + k0);
        float4 bv = *(const float4*)(Bp + (long)k0 * N);
        As[ac4+0][arow] = av.x; As[ac4+1][arow] = av.y;
        As[ac4+2][arow] = av.z; As[ac4+3][arow] = av.w;
        *(float4*)&Bs[brow][bc] = bv;
        __syncthreads();
        #pragma unroll
        for (int k = 0; k < 8; k++) {
            float a[8], b[8];
            #pragma unroll
            for (int i = 0; i < 8; i++) a[i] = As[k][row0 + i];
            #pragma unroll
            for (int j = 0; j < 8; j++) b[j] = Bs[k][col0 + j];
            #pragma unroll
            for (int i = 0; i < 8; i++)
                #pragma unroll
                for (int j = 0; j < 8; j++) acc[i][j] += a[i] * b[j];
        }
        __syncthreads();
    }

    #pragma unroll
    for (int i = 0; i < 8; i++) {
        float* Cp = C + (long)(m0 + row0 + i) * N + n0 + col0;
        #pragma unroll
        for (int j = 0; j < 8; j++) {
            float v = acc[i][j];
            if (EPI >= 1) v += bias[n0 + col0 + j];
            if (EPI == 2) v = fmaxf(v, 0.f);
            Cp[j] = v;
        }
    }
}

// ---------------- QK^T / QR^T batched, K=64, 64x64 tiles ----------------
// MODE 0: AC = (q+u) . k   (keys from qkv, per-b)
// MODE 1: preBD = (q+v) . r_h (keys from g_rh, b-independent B matrix)
template<int MODE>
__global__ void qk_kernel(const float* __restrict__ qkv, const float* __restrict__ uv,
                          float* __restrict__ out)
{
    const int i0 = blockIdx.x * 64;
    const int j0 = blockIdx.y * 64;
    const int bh = blockIdx.z;
    const int b = bh / NH, h = bh % NH;

    if (MODE == 0) { if (j0 > i0 + 63 + MEMLEN) return; }              // fully masked
    else           { if (j0 + 63 < (QLEN - 1) - (i0 + 63)) return; }   // m never gathered

    __shared__ float Asm[64][65];  // [d][i]
    __shared__ float Bsm[64][65];  // [d][j]
    const int tid = threadIdx.x;

    #pragma unroll
    for (int s = 0; s < 4; s++) {
        int idx4 = tid + 256 * s;
        int i = idx4 >> 4, d4 = idx4 & 15;
        float4 qv = *(const float4*)(qkv + ((long)((MEMLEN + i0 + i) * BATCH + b)) * 3072 + h * 64 + d4 * 4);
        float4 uvv = *(const float4*)(uv + h * 64 + d4 * 4);
        Asm[d4*4+0][i] = qv.x + uvv.x; Asm[d4*4+1][i] = qv.y + uvv.y;
        Asm[d4*4+2][i] = qv.z + uvv.z; Asm[d4*4+3][i] = qv.w + uvv.w;
    }
    #pragma unroll
    for (int s = 0; s < 4; s++) {
        int idx4 = tid + 256 * s;
        int j = idx4 >> 4, d4 = idx4 & 15;
        float4 kv;
        if (MODE == 0)
            kv = *(const float4*)(qkv + ((long)((j0 + j) * BATCH + b)) * 3072 + 1024 + h * 64 + d4 * 4);
        else
            kv = *(const float4*)(g_rh + (long)(j0 + j) * DMODEL + h * 64 + d4 * 4);
        Bsm[d4*4+0][j] = kv.x; Bsm[d4*4+1][j] = kv.y;
        Bsm[d4*4+2][j] = kv.z; Bsm[d4*4+3][j] = kv.w;
    }
    __syncthreads();

    const int ty = tid >> 4, tx = tid & 15;
    float acc[4][4];
    #pragma unroll
    for (int r = 0; r < 4; r++)
        #pragma unroll
        for (int c = 0; c < 4; c++) acc[r][c] = 0.f;

    #pragma unroll 8
    for (int d = 0; d < 64; d++) {
        float a[4], bb[4];
        #pragma unroll
        for (int r = 0; r < 4; r++) a[r] = Asm[d][ty*4+r];
        #pragma unroll
        for (int c = 0; c < 4; c++) bb[c] = Bsm[d][tx*4+c];
        #pragma unroll
        for (int r = 0; r < 4; r++)
            #pragma unroll
            for (int c = 0; c < 4; c++) acc[r][c] += a[r] * bb[c];
    }

    #pragma unroll
    for (int r = 0; r < 4; r++) {
        float* op = out + ((long)bh * QLEN + i0 + ty*4 + r) * KLEN + j0 + tx*4;
        #pragma unroll
        for (int c = 0; c < 4; c++) op[c] = acc[r][c];
    }
}

// ---------------- softmax with rel-shift gather + causal(+mem) mask -------------
// prob[i,j] = softmax_j( (AC[i,j] + preBD[i, j-i+QLEN-1]) * SCALE ), j <= i+MEMLEN
__global__ void softmax_kernel()
{
    const long row = blockIdx.x;                 // (b*NH + h)*QLEN + i
    const int i = (int)(row % QLEN);
    float* ac = g_score + row * KLEN;
    const float* bd = g_bd + row * KLEN;
    const int tid = threadIdx.x;
    const int jv = i + MEMLEN;                   // last valid key (inclusive)

    float vals[6];
    float mx = -1e30f;
    #pragma unroll
    for (int s = 0; s < 6; s++) {
        int j = tid + 256 * s;
        float x = -1e30f;
        if (j <= jv) x = (ac[j] + bd[j - i + QLEN - 1]) * 0.125f;
        vals[s] = x;
        mx = fmaxf(mx, x);
    }
    __shared__ float red[256];
    red[tid] = mx; __syncthreads();
    for (int o = 128; o > 0; o >>= 1) { if (tid < o) red[tid] = fmaxf(red[tid], red[tid + o]); __syncthreads(); }
    mx = red[0]; __syncthreads();

    float sum = 0.f;
    #pragma unroll
    for (int s = 0; s < 6; s++) {
        float e = (vals[s] > -1e29f) ? __expf(vals[s] - mx) : 0.f;
        vals[s] = e; sum += e;
    }
    red[tid] = sum; __syncthreads();
    for (int o = 128; o > 0; o >>= 1) { if (tid < o) red[tid] += red[tid + o]; __syncthreads(); }
    const float inv = 1.f / red[0];

    #pragma unroll
    for (int s = 0; s < 6; s++) {
        int j = tid + 256 * s;
        ac[j] = vals[s] * inv;
    }
}

// ---------------- ctx = attn @ V ----------------
__global__ void av_kernel(const float* __restrict__ qkv)
{
    const int i0 = blockIdx.x * 64;
    const int bh = blockIdx.y;
    const int b = bh / NH, h = bh % NH;
    __shared__ float Ps[16][65];  // [j][i]
    __shared__ float Vs[16][64];  // [j][d]
    const int tid = threadIdx.x;
    const int ty = tid >> 4, tx = tid & 15;

    float acc[4][4];
    #pragma unroll
    for (int r = 0; r < 4; r++)
        #pragma unroll
        for (int c = 0; c < 4; c++) acc[r][c] = 0.f;

    const int jmax = min(KLEN, i0 + 63 + MEMLEN + 1);   // multiple of 16
    const float* prow = g_score + ((long)bh * QLEN + i0) * KLEN;

    for (int jt = 0; jt < jmax; jt += 16) {
        {
            int i = tid >> 2, j4 = tid & 3;
            float4 pv = *(const float4*)(prow + (long)i * KLEN + jt + j4 * 4);
            Ps[j4*4+0][i] = pv.x; Ps[j4*4+1][i] = pv.y;
            Ps[j4*4+2][i] = pv.z; Ps[j4*4+3][i] = pv.w;
        }
        {
            int jr = tid >> 4, c4 = tid & 15;
            float4 vv = *(const float4*)(qkv + ((long)((jt + jr) * BATCH + b)) * 3072 + 2048 + h * 64 + c4 * 4);
            *(float4*)&Vs[jr][c4 * 4] = vv;
        }
        __syncthreads();
        #pragma unroll
        for (int j = 0; j < 16; j++) {
            float p[4], vv[4];
            #pragma unroll
            for (int r = 0; r < 4; r++) p[r] = Ps[j][ty*4+r];
            #pragma unroll
            for (int c = 0; c < 4; c++) vv[c] = Vs[j][tx*4+c];
            #pragma unroll
            for (int r = 0; r < 4; r++)
                #pragma unroll
                for (int c = 0; c < 4; c++) acc[r][c] += p[r] * vv[c];
        }
        __syncthreads();
    }

    #pragma unroll
    for (int r = 0; r < 4; r++)
        #pragma unroll
        for (int c = 0; c < 4; c++)
            g_ctx[((long)(i0 + ty*4 + r) * BATCH + b) * DMODEL + h * 64 + tx*4 + c] = acc[r][c];
}

// ---------------- LayerNorm(out = LN(a + bres) * g + bt), per 1024-row ----------
__global__ void ln_kernel(float* __restrict__ out, const float* __restrict__ a,
                          const float* __restrict__ bres,
                          const float* __restrict__ g, const float* __restrict__ bt)
{
    const long row = blockIdx.x;
    const float* pa = a + row * DMODEL;
    const float* pb = bres + row * DMODEL;
    const int tid = threadIdx.x;

    float v[4];
    float s = 0.f;
    #pragma unroll
    for (int q = 0; q < 4; q++) {
        int c = tid + 256 * q;
        v[q] = pa[c] + pb[c];
        s += v[q];
    }
    __shared__ float red[256];
    red[tid] = s; __syncthreads();
    for (int o = 128; o > 0; o >>= 1) { if (tid < o) red[tid] += red[tid + o]; __syncthreads(); }
    const float mean = red[0] * (1.f / DMODEL);
    __syncthreads();

    float vs = 0.f;
    #pragma unroll
    for (int q = 0; q < 4; q++) { float d = v[q] - mean; vs += d * d; }
    red[tid] = vs; __syncthreads();
    for (int o = 128; o > 0; o >>= 1) { if (tid < o) red[tid] += red[tid + o]; __syncthreads(); }
    const float inv = rsqrtf(red[0] * (1.f / DMODEL) + 1e-5f);

    #pragma unroll
    for (int q = 0; q < 4; q++) {
        int c = tid + 256 * q;
        out[row * DMODEL + c] = (v[q] - mean) * inv * g[c] + bt[c];
    }
}

// ---------------- host side ----------------
static inline float* devptr(const void* sym)
{
    void* p = nullptr;
    cudaGetSymbolAddress(&p, sym);
    return (float*)p;
}

extern "C" void kernel_launch(void* const* d_in, const int* in_sizes, int n_in,
                              void* d_out, int out_size)
{
    (void)in_sizes; (void)n_in; (void)out_size;
    const float* inputs = (const float*)d_in[0];
    const float* r      = (const float*)d_in[1];
    const float* u      = (const float*)d_in[2];
    const float* v      = (const float*)d_in[3];
    const float* mem    = (const float*)d_in[4];
    // d_in[5] = attn_mask (deterministic; recomputed analytically, not read)
    const float* W_qkv  = (const float*)d_in[6];
    const float* W_r    = (const float*)d_in[7];
    const float* W_o    = (const float*)d_in[8];
    const float* ln1g   = (const float*)d_in[9];
    const float* ln1b   = (const float*)d_in[10];
    const float* ln2g   = (const float*)d_in[11];
    const float* ln2b   = (const float*)d_in[12];
    const float* W1     = (const float*)d_in[13];
    const float* b1     = (const float*)d_in[14];
    const float* W2     = (const float*)d_in[15];
    const float* b2     = (const float*)d_in[16];
    float* out = (float*)d_out;

    float* p_cat   = devptr(g_cat);
    float* p_qkv   = devptr(g_qkv);
    float* p_rh    = devptr(g_rh);
    float* p_score = devptr(g_score);
    float* p_bd    = devptr(g_bd);
    float* p_ctx   = devptr(g_ctx);
    float* p_y     = devptr(g_y);
    float* p_x     = devptr(g_x);
    float* p_h     = devptr(g_h);
    float* p_y2    = devptr(g_y2);

    // 1. concat
    cat_kernel<<<CATROWS*DMODEL/4/256, 256>>>(mem, inputs);

    // 2. qkv = cat @ W_qkv   [6144,3072,1024]
    sgemm128<0><<<dim3(3072/128, CATROWS/128), 256>>>(p_cat, W_qkv, p_qkv, CATROWS, 3072, DMODEL, nullptr);

    // 3. r_h = r @ W_r       [1536,1024,1024]
    sgemm128<0><<<dim3(DMODEL/128, KLEN/128), 256>>>(r, W_r, p_rh, KLEN, DMODEL, DMODEL, nullptr);

    // 4. AC and preBD   (64 batched 1024x1536x64)
    qk_kernel<0><<<dim3(QLEN/64, KLEN/64, BATCH*NH), 256>>>(p_qkv, u, p_score);
    qk_kernel<1><<<dim3(QLEN/64, KLEN/64, BATCH*NH), 256>>>(p_qkv, v, p_bd);

    // 5. masked softmax with rel-shift (in-place into g_score)
    softmax_kernel<<<BATCH*NH*QLEN, 256>>>();

    // 6. ctx = attn @ V
    av_kernel<<<dim3(QLEN/64, BATCH*NH), 256>>>(p_qkv);

    // 7. y = ctx @ W_o
    sgemm128<0><<<dim3(DMODEL/128, ROWS/128), 256>>>(p_ctx, W_o, p_y, ROWS, DMODEL, DMODEL, nullptr);

    // 8. x = LN1(inputs + y)
    ln_kernel<<<ROWS, 256>>>(p_x, inputs, p_y, ln1g, ln1b);

    // 9. h = relu(x @ W1 + b1)
    sgemm128<2><<<dim3(MLPD/128, ROWS/128), 256>>>(p_x, W1, p_h, ROWS, MLPD, DMODEL, b1);

    // 10. y2 = h @ W2 + b2
    sgemm128<1><<<dim3(DMODEL/128, ROWS/128), 256>>>(p_h, W2, p_y2, ROWS, DMODEL, MLPD, b2);

    // 11. out = LN2(x + y2)
    ln_kernel<<<ROWS, 256>>>(out, p_x, p_y2, ln2g, ln2b);
}

// round 5
// speedup vs baseline: 1.3342x; 1.3342x over previous
#include <cuda_runtime.h>
#include <math.h>
#include <stdint.h>

// ---------------- problem constants ----------------
#define QLEN   1024
#define BATCH  4
#define DMODEL 1024
#define NH     16
#define HD     64
#define MEMLEN 512
#define KLEN   1536            // MEMLEN + QLEN
#define MLPD   4096
#define ROWS   (QLEN*BATCH)    // 4096
#define CATROWS (KLEN*BATCH)   // 6144

// ---------------- scratch (device globals; no allocation allowed) ----------------
__device__ __align__(128) float g_cat [CATROWS*DMODEL];
__device__ __align__(128) float g_qkv [CATROWS*3*DMODEL];
__device__ __align__(128) float g_rh  [KLEN*DMODEL];
__device__ __align__(128) float g_score[(size_t)BATCH*NH*QLEN*KLEN];
__device__ __align__(128) float g_bd  [(size_t)BATCH*NH*QLEN*KLEN];
__device__ __align__(128) float g_ctx [ROWS*DMODEL];
__device__ __align__(128) float g_y   [ROWS*DMODEL];
__device__ __align__(128) float g_x   [ROWS*DMODEL];
__device__ __align__(128) float g_h   [ROWS*MLPD];
__device__ __align__(128) float g_y2  [ROWS*DMODEL];
// transposed (K-major [N,K]) weights
__device__ __align__(128) float g_wqkv_t[3072*1024];
__device__ __align__(128) float g_wr_t  [1024*1024];
__device__ __align__(128) float g_wo_t  [1024*1024];
__device__ __align__(128) float g_w1_t  [4096*1024];
__device__ __align__(128) float g_w2_t  [1024*4096];

// ---------------- small PTX helpers ----------------
__device__ __forceinline__ uint32_t smem_u32(const void* p) {
    uint32_t a;
    asm("{ .reg .u64 t; cvta.to.shared.u64 t, %1; cvt.u32.u64 %0, t; }" : "=r"(a) : "l"(p));
    return a;
}
__device__ __forceinline__ void cp16(uint32_t dst, const void* src) {
    asm volatile("cp.async.cg.shared.global [%0], [%1], 16;" :: "r"(dst), "l"(src));
}
__device__ __forceinline__ uint32_t f2tf32(float f) {
    uint32_t u;
    asm("cvt.rna.tf32.f32 %0, %1;" : "=r"(u) : "f"(f));
    return u;
}

// ---------------- concat [mem; inputs] -> g_cat ----------------
__global__ void cat_kernel(const float* __restrict__ mem, const float* __restrict__ inp)
{
    int idx4 = blockIdx.x * blockDim.x + threadIdx.x;
    if (idx4 >= CATROWS*DMODEL/4) return;
    long e = (long)idx4 * 4;
    int kv  = (int)(e / (BATCH*DMODEL));
    int rem = (int)(e % (BATCH*DMODEL));
    const float* src = (kv < MEMLEN)
        ? mem + (long)kv*BATCH*DMODEL + rem
        : inp + (long)(kv-MEMLEN)*BATCH*DMODEL + rem;
    *(float4*)(g_cat + e) = *(const float4*)src;
}

// ---------------- W[K][N] -> Wt[N][K] transpose ----------------
__global__ void transpose_kernel(const float* __restrict__ W, float* __restrict__ Wt,
                                 int K, int N)
{
    __shared__ float t[32][33];
    int k0 = blockIdx.y * 32, n0 = blockIdx.x * 32;
    int tx = threadIdx.x, ty = threadIdx.y;         // 32 x 8
    #pragma unroll
    for (int s = 0; s < 32; s += 8)
        t[ty + s][tx] = W[(long)(k0 + ty + s) * N + n0 + tx];
    __syncthreads();
    #pragma unroll
    for (int s = 0; s < 32; s += 8)
        Wt[(long)(n0 + ty + s) * K + k0 + tx] = t[tx][ty + s];
}

// ============ tf32 mma.sync GEMM: C[M,N] = A[M,K] @ Bt[N,K]^T ==================
// EPI: 0 none, 1 +bias, 2 +bias+relu.  M,N multiples of 128; K multiple of 32.
// 256 threads (8 warps 2x4), block tile 128x128, K-chunk 32, cp.async 2-stage.
// SMEM per stage: A 128x36 + B 128x36 floats; total 2*9216*2*4 = 73728 bytes.
#define MMA_SMEM_BYTES (73728)

template<int EPI>
__global__ void __launch_bounds__(256)
mma_gemm(const float* __restrict__ A, const float* __restrict__ Bt,
         float* __restrict__ C, int M, int N, int K, const float* __restrict__ bias)
{
    extern __shared__ float smem[];
    const int tid = threadIdx.x, lane = tid & 31, warp = tid >> 5;
    const int wm = warp >> 2, wn = warp & 3;       // 2 x 4 warp grid
    const int m0 = blockIdx.y * 128, n0 = blockIdx.x * 128;

    const uint32_t sb = smem_u32(smem);
    // float offsets: stage s: A at s*9216, B at s*9216+4608
    const float* Ag = A + (long)m0 * K;
    const float* Bg = Bt + (long)n0 * K;

    const int rrow = tid >> 3, q = tid & 7;        // 32 rows/pass, 8 thr/row

    float c[4][4][4];                              // [mi][ni][reg]
    #pragma unroll
    for (int mi = 0; mi < 4; mi++)
        #pragma unroll
        for (int ni = 0; ni < 4; ni++)
            #pragma unroll
            for (int rix = 0; rix < 4; rix++) c[mi][ni][rix] = 0.f;

    const int nc = K >> 5;

    // ---- preload stage 0 ----
    {
        uint32_t dA = sb + (rrow * 36 + q * 4) * 4;
        uint32_t dB = dA + 4608 * 4;
        #pragma unroll
        for (int i = 0; i < 4; i++) {
            int row = i * 32 + rrow;
            cp16(dA + i * 32 * 36 * 4, Ag + (long)row * K + q * 4);
            cp16(dB + i * 32 * 36 * 4, Bg + (long)row * K + q * 4);
        }
        asm volatile("cp.async.commit_group;");
    }

    for (int cch = 0; cch < nc; cch++) {
        const int buf = cch & 1;
        if (cch + 1 < nc) {
            const int nb = buf ^ 1;
            const int k0 = (cch + 1) << 5;
            uint32_t dA = sb + (nb * 9216 + rrow * 36 + q * 4) * 4;
            uint32_t dB = dA + 4608 * 4;
            #pragma unroll
            for (int i = 0; i < 4; i++) {
                int row = i * 32 + rrow;
                cp16(dA + i * 32 * 36 * 4, Ag + (long)row * K + k0 + q * 4);
                cp16(dB + i * 32 * 36 * 4, Bg + (long)row * K + k0 + q * 4);
            }
            asm volatile("cp.async.commit_group;");
            asm volatile("cp.async.wait_group 1;");
        } else {
            asm volatile("cp.async.wait_group 0;");
        }
        __syncthreads();

        const float* sA = smem + buf * 9216;
        const float* sB = sA + 4608;
        const int arow = wm * 64 + (lane >> 2);
        const int brow = wn * 32 + (lane >> 2);
        const int kc = lane & 3;

        #pragma unroll
        for (int ks = 0; ks < 4; ks++) {
            const int kk = kc + ks * 8;
            uint32_t a[4][4], b[4][2];
            #pragma unroll
            for (int mi = 0; mi < 4; mi++) {
                const float* p = sA + (arow + mi * 16) * 36 + kk;
                a[mi][0] = f2tf32(p[0]);
                a[mi][1] = f2tf32(p[8 * 36]);
                a[mi][2] = f2tf32(p[4]);
                a[mi][3] = f2tf32(p[8 * 36 + 4]);
            }
            #pragma unroll
            for (int ni = 0; ni < 4; ni++) {
                const float* p = sB + (brow + ni * 8) * 36 + kk;
                b[ni][0] = f2tf32(p[0]);
                b[ni][1] = f2tf32(p[4]);
            }
            #pragma unroll
            for (int mi = 0; mi < 4; mi++)
                #pragma unroll
                for (int ni = 0; ni < 4; ni++)
                    asm volatile(
                        "mma.sync.aligned.m16n8k8.row.col.f32.tf32.tf32.f32 "
                        "{%0,%1,%2,%3},{%4,%5,%6,%7},{%8,%9},{%0,%1,%2,%3};"
                        : "+f"(c[mi][ni][0]), "+f"(c[mi][ni][1]),
                          "+f"(c[mi][ni][2]), "+f"(c[mi][ni][3])
                        : "r"(a[mi][0]), "r"(a[mi][1]), "r"(a[mi][2]), "r"(a[mi][3]),
                          "r"(b[ni][0]), "r"(b[ni][1]));
        }
        __syncthreads();
    }

    // ---- epilogue: direct float2 stores with optional bias/relu ----
    const int crow = m0 + wm * 64 + (lane >> 2);
    const int ccol = n0 + wn * 32 + 2 * (lane & 3);
    #pragma unroll
    for (int ni = 0; ni < 4; ni++) {
        const int col = ccol + ni * 8;
        float bx = 0.f, by = 0.f;
        if (EPI >= 1) { bx = bias[col]; by = bias[col + 1]; }
        #pragma unroll
        for (int mi = 0; mi < 4; mi++) {
            const int row = crow + mi * 16;
            float v0 = c[mi][ni][0], v1 = c[mi][ni][1];
            float v2 = c[mi][ni][2], v3 = c[mi][ni][3];
            if (EPI >= 1) { v0 += bx; v1 += by; v2 += bx; v3 += by; }
            if (EPI == 2) {
                v0 = fmaxf(v0, 0.f); v1 = fmaxf(v1, 0.f);
                v2 = fmaxf(v2, 0.f); v3 = fmaxf(v3, 0.f);
            }
            *(float2*)(C + (long)row * N + col)       = make_float2(v0, v1);
            *(float2*)(C + (long)(row + 8) * N + col) = make_float2(v2, v3);
        }
    }
}

// ---------------- QK^T / QR^T batched, K=64, 64x64 tiles ----------------
template<int MODE>
__global__ void qk_kernel(const float* __restrict__ qkv, const float* __restrict__ uv,
                          float* __restrict__ out)
{
    const int i0 = blockIdx.x * 64;
    const int j0 = blockIdx.y * 64;
    const int bh = blockIdx.z;
    const int b = bh / NH, h = bh % NH;

    if (MODE == 0) { if (j0 > i0 + 63 + MEMLEN) return; }
    else           { if (j0 + 63 < (QLEN - 1) - (i0 + 63)) return; }

    __shared__ float Asm[64][65];
    __shared__ float Bsm[64][65];
    const int tid = threadIdx.x;

    #pragma unroll
    for (int s = 0; s < 4; s++) {
        int idx4 = tid + 256 * s;
        int i = idx4 >> 4, d4 = idx4 & 15;
        float4 qv = *(const float4*)(qkv + ((long)((MEMLEN + i0 + i) * BATCH + b)) * 3072 + h * 64 + d4 * 4);
        float4 uvv = *(const float4*)(uv + h * 64 + d4 * 4);
        Asm[d4*4+0][i] = qv.x + uvv.x; Asm[d4*4+1][i] = qv.y + uvv.y;
        Asm[d4*4+2][i] = qv.z + uvv.z; Asm[d4*4+3][i] = qv.w + uvv.w;
    }
    #pragma unroll
    for (int s = 0; s < 4; s++) {
        int idx4 = tid + 256 * s;
        int j = idx4 >> 4, d4 = idx4 & 15;
        float4 kv;
        if (MODE == 0)
            kv = *(const float4*)(qkv + ((long)((j0 + j) * BATCH + b)) * 3072 + 1024 + h * 64 + d4 * 4);
        else
            kv = *(const float4*)(g_rh + (long)(j0 + j) * DMODEL + h * 64 + d4 * 4);
        Bsm[d4*4+0][j] = kv.x; Bsm[d4*4+1][j] = kv.y;
        Bsm[d4*4+2][j] = kv.z; Bsm[d4*4+3][j] = kv.w;
    }
    __syncthreads();

    const int ty = tid >> 4, tx = tid & 15;
    float acc[4][4];
    #pragma unroll
    for (int r = 0; r < 4; r++)
        #pragma unroll
        for (int c = 0; c < 4; c++) acc[r][c] = 0.f;

    #pragma unroll 8
    for (int d = 0; d < 64; d++) {
        float a[4], bb[4];
        #pragma unroll
        for (int r = 0; r < 4; r++) a[r] = Asm[d][ty*4+r];
        #pragma unroll
        for (int c = 0; c < 4; c++) bb[c] = Bsm[d][tx*4+c];
        #pragma unroll
        for (int r = 0; r < 4; r++)
            #pragma unroll
            for (int c = 0; c < 4; c++) acc[r][c] += a[r] * bb[c];
    }

    #pragma unroll
    for (int r = 0; r < 4; r++) {
        float* op = out + ((long)bh * QLEN + i0 + ty*4 + r) * KLEN + j0 + tx*4;
        #pragma unroll
        for (int c = 0; c < 4; c++) op[c] = acc[r][c];
    }
}

// ---------------- softmax with rel-shift gather + causal(+mem) mask -------------
__global__ void softmax_kernel()
{
    const long row = blockIdx.x;
    const int i = (int)(row % QLEN);
    float* ac = g_score + row * KLEN;
    const float* bd = g_bd + row * KLEN;
    const int tid = threadIdx.x;
    const int jv = i + MEMLEN;

    float vals[6];
    float mx = -1e30f;
    #pragma unroll
    for (int s = 0; s < 6; s++) {
        int j = tid + 256 * s;
        float x = -1e30f;
        if (j <= jv) x = (ac[j] + bd[j - i + QLEN - 1]) * 0.125f;
        vals[s] = x;
        mx = fmaxf(mx, x);
    }
    __shared__ float red[256];
    red[tid] = mx; __syncthreads();
    for (int o = 128; o > 0; o >>= 1) { if (tid < o) red[tid] = fmaxf(red[tid], red[tid + o]); __syncthreads(); }
    mx = red[0]; __syncthreads();

    float sum = 0.f;
    #pragma unroll
    for (int s = 0; s < 6; s++) {
        float e = (vals[s] > -1e29f) ? __expf(vals[s] - mx) : 0.f;
        vals[s] = e; sum += e;
    }
    red[tid] = sum; __syncthreads();
    for (int o = 128; o > 0; o >>= 1) { if (tid < o) red[tid] += red[tid + o]; __syncthreads(); }
    const float inv = 1.f / red[0];

    #pragma unroll
    for (int s = 0; s < 6; s++) {
        int j = tid + 256 * s;
        ac[j] = vals[s] * inv;
    }
}

// ---------------- ctx = attn @ V ----------------
__global__ void av_kernel(const float* __restrict__ qkv)
{
    const int i0 = blockIdx.x * 64;
    const int bh = blockIdx.y;
    const int b = bh / NH, h = bh % NH;
    __shared__ float Ps[16][65];
    __shared__ float Vs[16][64];
    const int tid = threadIdx.x;
    const int ty = tid >> 4, tx = tid & 15;

    float acc[4][4];
    #pragma unroll
    for (int r = 0; r < 4; r++)
        #pragma unroll
        for (int c = 0; c < 4; c++) acc[r][c] = 0.f;

    const int jmax = min(KLEN, i0 + 63 + MEMLEN + 1);
    const float* prow = g_score + ((long)bh * QLEN + i0) * KLEN;

    for (int jt = 0; jt < jmax; jt += 16) {
        {
            int i = tid >> 2, j4 = tid & 3;
            float4 pv = *(const float4*)(prow + (long)i * KLEN + jt + j4 * 4);
            Ps[j4*4+0][i] = pv.x; Ps[j4*4+1][i] = pv.y;
            Ps[j4*4+2][i] = pv.z; Ps[j4*4+3][i] = pv.w;
        }
        {
            int jr = tid >> 4, c4 = tid & 15;
            float4 vv = *(const float4*)(qkv + ((long)((jt + jr) * BATCH + b)) * 3072 + 2048 + h * 64 + c4 * 4);
            *(float4*)&Vs[jr][c4 * 4] = vv;
        }
        __syncthreads();
        #pragma unroll
        for (int j = 0; j < 16; j++) {
            float p[4], vv[4];
            #pragma unroll
            for (int r = 0; r < 4; r++) p[r] = Ps[j][ty*4+r];
            #pragma unroll
            for (int c = 0; c < 4; c++) vv[c] = Vs[j][tx*4+c];
            #pragma unroll
            for (int r = 0; r < 4; r++)
                #pragma unroll
                for (int c = 0; c < 4; c++) acc[r][c] += p[r] * vv[c];
        }
        __syncthreads();
    }

    #pragma unroll
    for (int r = 0; r < 4; r++)
        #pragma unroll
        for (int c = 0; c < 4; c++)
            g_ctx[((long)(i0 + ty*4 + r) * BATCH + b) * DMODEL + h * 64 + tx*4 + c] = acc[r][c];
}

// ---------------- LayerNorm ----------------
__global__ void ln_kernel(float* __restrict__ out, const float* __restrict__ a,
                          const float* __restrict__ bres,
                          const float* __restrict__ g, const float* __restrict__ bt)
{
    const long row = blockIdx.x;
    const float* pa = a + row * DMODEL;
    const float* pb = bres + row * DMODEL;
    const int tid = threadIdx.x;

    float v[4];
    float s = 0.f;
    #pragma unroll
    for (int q = 0; q < 4; q++) {
        int c = tid + 256 * q;
        v[q] = pa[c] + pb[c];
        s += v[q];
    }
    __shared__ float red[256];
    red[tid] = s; __syncthreads();
    for (int o = 128; o > 0; o >>= 1) { if (tid < o) red[tid] += red[tid + o]; __syncthreads(); }
    const float mean = red[0] * (1.f / DMODEL);
    __syncthreads();

    float vs = 0.f;
    #pragma unroll
    for (int q = 0; q < 4; q++) { float d = v[q] - mean; vs += d * d; }
    red[tid] = vs; __syncthreads();
    for (int o = 128; o > 0; o >>= 1) { if (tid < o) red[tid] += red[tid + o]; __syncthreads(); }
    const float inv = rsqrtf(red[0] * (1.f / DMODEL) + 1e-5f);

    #pragma unroll
    for (int q = 0; q < 4; q++) {
        int c = tid + 256 * q;
        out[row * DMODEL + c] = (v[q] - mean) * inv * g[c] + bt[c];
    }
}

// ---------------- host side ----------------
static inline float* devptr(const void* sym)
{
    void* p = nullptr;
    cudaGetSymbolAddress(&p, sym);
    return (float*)p;
}

extern "C" void kernel_launch(void* const* d_in, const int* in_sizes, int n_in,
                              void* d_out, int out_size)
{
    (void)in_sizes; (void)n_in; (void)out_size;
    const float* inputs = (const float*)d_in[0];
    const float* r      = (const float*)d_in[1];
    const float* u      = (const float*)d_in[2];
    const float* v      = (const float*)d_in[3];
    const float* mem    = (const float*)d_in[4];
    // d_in[5] = attn_mask (deterministic; recomputed analytically)
    const float* W_qkv  = (const float*)d_in[6];
    const float* W_r    = (const float*)d_in[7];
    const float* W_o    = (const float*)d_in[8];
    const float* ln1g   = (const float*)d_in[9];
    const float* ln1b   = (const float*)d_in[10];
    const float* ln2g   = (const float*)d_in[11];
    const float* ln2b   = (const float*)d_in[12];
    const float* W1     = (const float*)d_in[13];
    const float* b1     = (const float*)d_in[14];
    const float* W2     = (const float*)d_in[15];
    const float* b2     = (const float*)d_in[16];
    float* out = (float*)d_out;

    float* p_cat   = devptr(g_cat);
    float* p_qkv   = devptr(g_qkv);
    float* p_rh    = devptr(g_rh);
    float* p_score = devptr(g_score);
    float* p_bd    = devptr(g_bd);
    float* p_ctx   = devptr(g_ctx);
    float* p_y     = devptr(g_y);
    float* p_x     = devptr(g_x);
    float* p_h     = devptr(g_h);
    float* p_y2    = devptr(g_y2);
    float* p_wqkv_t = devptr(g_wqkv_t);
    float* p_wr_t   = devptr(g_wr_t);
    float* p_wo_t   = devptr(g_wo_t);
    float* p_w1_t   = devptr(g_w1_t);
    float* p_w2_t   = devptr(g_w2_t);

    cudaFuncSetAttribute(mma_gemm<0>, cudaFuncAttributeMaxDynamicSharedMemorySize, MMA_SMEM_BYTES);
    cudaFuncSetAttribute(mma_gemm<1>, cudaFuncAttributeMaxDynamicSharedMemorySize, MMA_SMEM_BYTES);
    cudaFuncSetAttribute(mma_gemm<2>, cudaFuncAttributeMaxDynamicSharedMemorySize, MMA_SMEM_BYTES);

    dim3 tb(32, 8);
    // weight transposes (K-major [N,K])
    transpose_kernel<<<dim3(3072/32, 1024/32), tb>>>(W_qkv, p_wqkv_t, 1024, 3072);
    transpose_kernel<<<dim3(1024/32, 1024/32), tb>>>(W_r,   p_wr_t,   1024, 1024);
    transpose_kernel<<<dim3(1024/32, 1024/32), tb>>>(W_o,   p_wo_t,   1024, 1024);
    transpose_kernel<<<dim3(4096/32, 1024/32), tb>>>(W1,    p_w1_t,   1024, 4096);
    transpose_kernel<<<dim3(1024/32, 4096/32), tb>>>(W2,    p_w2_t,   4096, 1024);

    // 1. concat
    cat_kernel<<<CATROWS*DMODEL/4/256, 256>>>(mem, inputs);

    // 2. qkv = cat @ W_qkv   [6144 x 3072 x 1024]
    mma_gemm<0><<<dim3(3072/128, CATROWS/128), 256, MMA_SMEM_BYTES>>>(p_cat, p_wqkv_t, p_qkv, CATROWS, 3072, DMODEL, nullptr);

    // 3. r_h = r @ W_r       [1536 x 1024 x 1024]
    mma_gemm<0><<<dim3(DMODEL/128, KLEN/128), 256, MMA_SMEM_BYTES>>>(r, p_wr_t, p_rh, KLEN, DMODEL, DMODEL, nullptr);

    // 4. AC and preBD
    qk_kernel<0><<<dim3(QLEN/64, KLEN/64, BATCH*NH), 256>>>(p_qkv, u, p_score);
    qk_kernel<1><<<dim3(QLEN/64, KLEN/64, BATCH*NH), 256>>>(p_qkv, v, p_bd);

    // 5. masked softmax with rel-shift
    softmax_kernel<<<BATCH*NH*QLEN, 256>>>();

    // 6. ctx = attn @ V
    av_kernel<<<dim3(QLEN/64, BATCH*NH), 256>>>(p_qkv);

    // 7. y = ctx @ W_o
    mma_gemm<0><<<dim3(DMODEL/128, ROWS/128), 256, MMA_SMEM_BYTES>>>(p_ctx, p_wo_t, p_y, ROWS, DMODEL, DMODEL, nullptr);

    // 8. x = LN1(inputs + y)
    ln_kernel<<<ROWS, 256>>>(p_x, inputs, p_y, ln1g, ln1b);

    // 9. h = relu(x @ W1 + b1)
    mma_gemm<2><<<dim3(MLPD/128, ROWS/128), 256, MMA_SMEM_BYTES>>>(p_x, p_w1_t, p_h, ROWS, MLPD, DMODEL, b1);

    // 10. y2 = h @ W2 + b2
    mma_gemm<1><<<dim3(DMODEL/128, ROWS/128), 256, MMA_SMEM_BYTES>>>(p_h, p_w2_t, p_y2, ROWS, DMODEL, MLPD, b2);

    // 11. out = LN2(x + y2)
    ln_kernel<<<ROWS, 256>>>(out, p_x, p_y2, ln2g, ln2b);
}